// round 6
// baseline (speedup 1.0000x reference)
#include <cuda_runtime.h>

// FIR: out[b,t,c] = sum_{i=0..15} w[i,c] * x[b, t-15+i, c]   (causal, zero-padded)
// x: [B=64, T=2048, C=32] fp32, w: [F=16, C=32] fp32, out: [B, T, C] fp32.
//
// Round 6: SMEM-staged 256-timestep tile (LTS traffic ~= floor), packed f32x2
// math, full 31-entry packed window front-batched from SMEM via cheap LDS.64
// (29 cyc, no long-scoreboard exposure). 1 barrier per ~380 instructions.

#define B_SZ 64
#define T_SZ 2048
#define C_SZ 32
#define F_SZ 16
#define GRP  16
#define HALO (F_SZ - 1)                  // 15
#define NPAIR (C_SZ / 2)                 // 16
#define TILE_T 256
#define THREADS 256                      // 16 time-groups x 16 channel-pairs

#define SMEM_T (TILE_T + HALO)           // 271 rows
#define SMEM_FLOATS (SMEM_T * C_SZ)      // 8672
#define SMEM_VEC (SMEM_FLOATS / 4)       // 2168 float4
#define ZERO_VEC ((HALO * C_SZ) / 4)     // 120 leading zero-vectors when t0==0

typedef unsigned long long u64;

__device__ __forceinline__ u64 fma2(u64 a, u64 b, u64 c) {
    u64 d;
    asm("fma.rn.f32x2 %0, %1, %2, %3;" : "=l"(d) : "l"(a), "l"(b), "l"(c));
    return d;
}
__device__ __forceinline__ u64 add2(u64 a, u64 b) {
    u64 d;
    asm("add.rn.f32x2 %0, %1, %2;" : "=l"(d) : "l"(a), "l"(b));
    return d;
}

__global__ __launch_bounds__(THREADS, 2)
void fir_kernel(const float* __restrict__ x,
                const float* __restrict__ w,
                float* __restrict__ out) {
    __shared__ float4 tile[SMEM_VEC];

    const int tid = threadIdx.x;
    const int b   = blockIdx.x;
    const int t0  = blockIdx.y * TILE_T;

    // ---- taps for this thread's channel pair (front-batched, L2-hot) ----
    const int cp = tid & (NPAIR - 1);
    u64 wp[F_SZ];
    const u64* wpr = (const u64*)w;              // [16][16] pairs
#pragma unroll
    for (int i = 0; i < F_SZ; i++) wp[i] = wpr[i * NPAIR + cp];

    // ---- cooperative staging: gmem [t0-15 .. t0+255] x [0..31] -> smem ----
    const long gbase = ((long)b * T_SZ + t0 - HALO) * C_SZ;   // 128B-aligned
    const float4* gx = (const float4*)(x + gbase);

    if (t0 != 0) {
#pragma unroll
        for (int k = 0; k < 9; k++) {
            const int v = tid + k * THREADS;
            if (v < SMEM_VEC) tile[v] = gx[v];
        }
    } else {
#pragma unroll
        for (int k = 0; k < 9; k++) {
            const int v = tid + k * THREADS;
            if (v < SMEM_VEC)
                tile[v] = (v < ZERO_VEC) ? make_float4(0.f, 0.f, 0.f, 0.f) : gx[v];
        }
    }
    __syncthreads();

    // ---- compute: thread = channel pair cp, local rows u0..u0+15 ----
    const int u0 = (tid >> 4) * GRP;             // 0,16,...,240
    const u64* smp = (const u64*)tile;           // packed pairs, 16 per row

    // full packed window from SMEM: win[j] = row (u0 + j), j = 0..30
    u64 win[2 * F_SZ - 1];
#pragma unroll
    for (int j = 0; j < 2 * F_SZ - 1; j++)
        win[j] = smp[(u0 + j) * NPAIR + cp];

    u64* op = (u64*)out + ((long)b * T_SZ + t0 + u0) * NPAIR + cp;

#pragma unroll
    for (int u = 0; u < GRP; u++) {
        u64 acc0 = 0ULL, acc1 = 0ULL;            // 2 chains, dep depth 8
#pragma unroll
        for (int i = 0; i < F_SZ; i += 2) {
            acc0 = fma2(wp[i],     win[u + i],     acc0);
            acc1 = fma2(wp[i + 1], win[u + i + 1], acc1);
        }
        op[u * NPAIR] = add2(acc0, acc1);
    }
}

extern "C" void kernel_launch(void* const* d_in, const int* in_sizes, int n_in,
                              void* d_out, int out_size) {
    const float* x = (const float*)d_in[0];   // [64, 2048, 32]
    const float* w = (const float*)d_in[1];   // [16, 32]
    float* out = (float*)d_out;

    dim3 grid(B_SZ, T_SZ / TILE_T);           // (64, 8) = 512 blocks
    fir_kernel<<<grid, THREADS>>>(x, w, out);
}

// round 8
// speedup vs baseline: 1.5598x; 1.5598x over previous
#include <cuda_runtime.h>

// FIR: out[b,t,c] = sum_{i=0..15} w[i,c] * x[b, t-15+i, c]   (causal, zero-padded)
// x: [B=64, T=2048, C=32] fp32, w: [F=16, C=32] fp32, out: [B, T, C] fp32.
//
// Round 8: R7 with the halo zero-padding bug fixed (per-element t>=0 predicate
// -- also guards cross-batch reads). Thread = channel pair x 8 timesteps,
// 23-entry packed register window, fma.rn.f32x2, no smem, no barriers.

#define B_SZ 64
#define T_SZ 2048
#define C_SZ 32
#define F_SZ 16
#define GRP  8
#define HALO (F_SZ - 1)          // 15
#define WIN  (GRP + HALO)        // 23
#define NPAIR (C_SZ / 2)         // 16
#define THREADS 128

typedef unsigned long long u64;

__device__ __forceinline__ u64 fma2(u64 a, u64 b, u64 c) {
    u64 d;
    asm("fma.rn.f32x2 %0, %1, %2, %3;" : "=l"(d) : "l"(a), "l"(b), "l"(c));
    return d;
}
__device__ __forceinline__ u64 add2(u64 a, u64 b) {
    u64 d;
    asm("add.rn.f32x2 %0, %1, %2;" : "=l"(d) : "l"(a), "l"(b));
    return d;
}

__global__ __launch_bounds__(THREADS)
void fir_kernel(const float* __restrict__ x,
                const float* __restrict__ w,
                float* __restrict__ out) {
    // item id -> (b, time-group, channel-pair); consecutive lanes step cp,
    // so each half-warp covers 16 consecutive u64 = one 128B sector.
    const int g  = blockIdx.x * THREADS + threadIdx.x;
    const int cp = g & (NPAIR - 1);
    const int tg = (g >> 4) & (T_SZ / GRP - 1);   // 0..255
    const int b  = g >> 12;
    const int t0 = tg * GRP;

    const long base = ((long)b * T_SZ + t0) * NPAIR + cp;
    const u64* xp = (const u64*)x + base;

    // taps for this channel pair (L2/L1-hot)
    u64 wp[F_SZ];
    const u64* wpr = (const u64*)w;               // [16][16] pairs
#pragma unroll
    for (int i = 0; i < F_SZ; i++) wp[i] = wpr[i * NPAIR + cp];

    // packed window: win[j] = x-pair at batch-local time t0 - 15 + j, j = 0..22.
    // Halo entries with t < 0 are zero (also prevents cross-batch reads).
#pragma unroll 1
    {} // (keep compiler from merging the two loops' predicates)
    u64 win[WIN];
#pragma unroll
    for (int j = 0; j < HALO; j++) {
        const int t = t0 - HALO + j;
        win[j] = (t >= 0) ? xp[(j - HALO) * NPAIR] : 0ULL;
    }
#pragma unroll
    for (int j = 0; j < GRP; j++)
        win[HALO + j] = xp[j * NPAIR];

    u64* op = (u64*)out + base;

#pragma unroll
    for (int u = 0; u < GRP; u++) {
        u64 acc0 = 0ULL, acc1 = 0ULL;             // 2 chains, dep depth 8
#pragma unroll
        for (int i = 0; i < F_SZ; i += 2) {
            acc0 = fma2(wp[i],     win[u + i],     acc0);
            acc1 = fma2(wp[i + 1], win[u + i + 1], acc1);
        }
        op[u * NPAIR] = add2(acc0, acc1);
    }
}

extern "C" void kernel_launch(void* const* d_in, const int* in_sizes, int n_in,
                              void* d_out, int out_size) {
    const float* x = (const float*)d_in[0];   // [64, 2048, 32]
    const float* w = (const float*)d_in[1];   // [16, 32]
    float* out = (float*)d_out;

    const int total = B_SZ * (T_SZ / GRP) * NPAIR;       // 262144 threads
    fir_kernel<<<total / THREADS, THREADS>>>(x, w, out); // 2048 blocks
}

// round 9
// speedup vs baseline: 1.9669x; 1.2610x over previous
#include <cuda_runtime.h>

// FIR: out[b,t,c] = sum_{i=0..15} w[i,c] * x[b, t-15+i, c]   (causal, zero-padded)
// x: [B=64, T=2048, C=32] fp32, w: [F=16, C=32] fp32, out: [B, T, C] fp32.
//
// Round 9: streaming-accumulator form. Thread = channel pair x 8 timesteps.
// Hold 8 packed accumulators; stream the 23 window values, each consumed by
// <=8 fma.rn.f32x2 and discarded. __launch_bounds__(128,8) caps regs at 64:
// ~2x occupancy vs R8 AND bounds the load front-batch (MLP_p1 ~6-8 instead of
// 39), avoiding the cross-CTA L1tex-queue spread that pinned R2-R8 at ~9.5us.

#define B_SZ 64
#define T_SZ 2048
#define C_SZ 32
#define F_SZ 16
#define GRP  8
#define HALO (F_SZ - 1)          // 15
#define WIN  (GRP + HALO)        // 23
#define NPAIR (C_SZ / 2)         // 16
#define THREADS 128

typedef unsigned long long u64;

__device__ __forceinline__ u64 fma2(u64 a, u64 b, u64 c) {
    u64 d;
    asm("fma.rn.f32x2 %0, %1, %2, %3;" : "=l"(d) : "l"(a), "l"(b), "l"(c));
    return d;
}

__global__ __launch_bounds__(THREADS, 8)   // cap 64 regs/thread
void fir_kernel(const float* __restrict__ x,
                const float* __restrict__ w,
                float* __restrict__ out) {
    // item id -> (b, time-group, channel-pair); lanes 0..15 share (b,tg) and
    // step cp -> each half-warp LDG.64 covers one 128B line.
    const int g  = blockIdx.x * THREADS + threadIdx.x;
    const int cp = g & (NPAIR - 1);
    const int tg = (g >> 4) & (T_SZ / GRP - 1);   // 0..255
    const int b  = g >> 12;
    const int t0 = tg * GRP;

    const long base = ((long)b * T_SZ + t0) * NPAIR + cp;
    const u64* xp = (const u64*)x + base;

    // taps for this channel pair (L1-hot after first warp per SM)
    u64 wp[F_SZ];
    const u64* wpr = (const u64*)w;               // [16][16] pairs
#pragma unroll
    for (int i = 0; i < F_SZ; i++) wp[i] = wpr[i * NPAIR + cp];

    u64 acc[GRP];
#pragma unroll
    for (int u = 0; u < GRP; u++) acc[u] = 0ULL;

    if (t0 >= F_SZ) {
        // common path: full halo in-bounds, no predicates
#pragma unroll
        for (int j = 0; j < WIN; j++) {
            const u64 xv = xp[(j - HALO) * NPAIR];
            const int ulo = (j - HALO < 0) ? 0 : j - HALO;
            const int uhi = (j < GRP - 1) ? j : GRP - 1;
#pragma unroll
            for (int u = ulo; u <= uhi; u++)
                acc[u] = fma2(wp[j - u], xv, acc[u]);
        }
    } else {
        // t0 in {0, 8}: zero-pad (also blocks cross-batch reads)
#pragma unroll
        for (int j = 0; j < WIN; j++) {
            const int t = t0 - HALO + j;
            const u64 xv = (t >= 0) ? xp[(j - HALO) * NPAIR] : 0ULL;
            const int ulo = (j - HALO < 0) ? 0 : j - HALO;
            const int uhi = (j < GRP - 1) ? j : GRP - 1;
#pragma unroll
            for (int u = ulo; u <= uhi; u++)
                acc[u] = fma2(wp[j - u], xv, acc[u]);
        }
    }

    u64* op = (u64*)out + base;
#pragma unroll
    for (int u = 0; u < GRP; u++)
        op[u * NPAIR] = acc[u];
}

extern "C" void kernel_launch(void* const* d_in, const int* in_sizes, int n_in,
                              void* d_out, int out_size) {
    const float* x = (const float*)d_in[0];   // [64, 2048, 32]
    const float* w = (const float*)d_in[1];   // [16, 32]
    float* out = (float*)d_out;

    const int total = B_SZ * (T_SZ / GRP) * NPAIR;       // 262144 threads
    fir_kernel<<<total / THREADS, THREADS>>>(x, w, out); // 2048 blocks
}